// round 5
// baseline (speedup 1.0000x reference)
#include <cuda_runtime.h>
#include <cuda_fp16.h>

// HashGrid1D on GB300 — R5.
// Latency-bound at 50% occupancy => shrink smem to 65.5KB (levels 0..8,
// pair-packed half4) so 3 CTAs x 512 threads co-reside (75% occ).
// Levels 9..11: pair-packed half4 in global (L2-resident), prefetched early.
// Per point: 9 LDS.64 + 3 LDG.64 + 12 STG.64, all arithmetic fp32.

#define HASH_N    16384
#define HASH_MASK 16383
#define SMEM_PAIRS 8185             // sum_{l=0}^{8} ((16<<l)+1)
#define TBL_SCALE     16384.0f      // 2^14
#define TBL_INV_SCALE 6.103515625e-05f  // exact 2^-14

__device__ uint2 g_pair[3][HASH_N];   // levels 9,10,11: half4 {e0.x,e0.y,e1.x,e1.y}

__device__ __forceinline__ uint2 pack_pair(float2 a, float2 b)
{
    uint2 v;
    __half2 ha = __floats2half2_rn(a.x * TBL_SCALE, a.y * TBL_SCALE);
    __half2 hb = __floats2half2_rn(b.x * TBL_SCALE, b.y * TBL_SCALE);
    v.x = *reinterpret_cast<unsigned*>(&ha);
    v.y = *reinterpret_cast<unsigned*>(&hb);
    return v;
}

__device__ __forceinline__ void unpack_lerp_store(uint2 v, float w, float* dst)
{
    __half2 h0 = *reinterpret_cast<__half2*>(&v.x);
    __half2 h1 = *reinterpret_cast<__half2*>(&v.y);
    float2 e0 = __half22float2(h0);
    float2 e1 = __half22float2(h1);
    float2 r;
    r.x = fmaf(w, e1.x - e0.x, e0.x) * TBL_INV_SCALE;
    r.y = fmaf(w, e1.y - e0.y, e0.y) * TBL_INV_SCALE;
    *reinterpret_cast<float2*>(dst) = r;
}

__global__ void build_pairs_kernel(const float* __restrict__ table)
{
    int i = blockIdx.x * blockDim.x + threadIdx.x;
    if (i >= HASH_N) return;
    int inext = (i + 1) & HASH_MASK;
    #pragma unroll
    for (int k = 0; k < 3; ++k) {
        int l = 9 + k;
        float2 a = *reinterpret_cast<const float2*>(table + i     * 24 + 2 * l);
        float2 b = *reinterpret_cast<const float2*>(table + inext * 24 + 2 * l);
        g_pair[k][i] = pack_pair(a, b);
    }
}

__global__ void __launch_bounds__(512, 3)
hashgrid1d_kernel(const float* __restrict__ x,
                  const float* __restrict__ table,
                  float* __restrict__ out,
                  int n)
{
    extern __shared__ uint2 spair[];   // SMEM_PAIRS half4 entries

    const int off[10] = {0, 17, 50, 115, 244, 501, 1014, 2039, 4088, 8185};

    // ---- one-time fill: fp32 table -> scaled half4 pairs (levels 0..8) ----
    for (int e = threadIdx.x; e < SMEM_PAIRS; e += blockDim.x) {
        int l = 0;
        #pragma unroll
        for (int k = 1; k < 9; ++k) l += (e >= off[k]);
        int i = e - off[l];                 // i in [0, 16<<l]; i+1 <= 4097, no wrap
        float2 a = *reinterpret_cast<const float2*>(table + i       * 24 + 2 * l);
        float2 b = *reinterpret_cast<const float2*>(table + (i + 1) * 24 + 2 * l);
        spair[e] = pack_pair(a, b);
    }
    __syncthreads();

    int stride = gridDim.x * blockDim.x;
    for (int b = blockIdx.x * blockDim.x + threadIdx.x; b < n; b += stride) {
        float xv = __ldg(x + b);
        float xc = fminf(fmaxf(xv, 0.0f), 1.0f);
        float* orow = out + (size_t)b * 24;

        // ---- prefetch divergent global gathers (levels 9..11) first ----
        float pos9  = xc * 8192.0f;
        float pos10 = xc * 16384.0f;
        float pos11 = xc * 32768.0f;
        int   i9  = __float2int_rd(pos9);
        int   i10 = __float2int_rd(pos10);
        int   i11 = __float2int_rd(pos11);
        uint2 v9  = __ldg(&g_pair[0][i9  & HASH_MASK]);
        uint2 v10 = __ldg(&g_pair[1][i10 & HASH_MASK]);
        uint2 v11 = __ldg(&g_pair[2][i11 & HASH_MASK]);

        // ---- smem levels 0..8 while gathers are in flight ----
        float res = 16.0f;
        #pragma unroll
        for (int l = 0; l < 9; ++l) {
            float pos = xc * res;
            int   i0  = __float2int_rd(pos);
            float w   = pos - (float)i0;
            uint2 v   = spair[off[l] + i0];
            unpack_lerp_store(v, w, orow + 2 * l);
            res *= 2.0f;
        }

        // ---- consume prefetched levels 9..11 ----
        unpack_lerp_store(v9,  pos9  - (float)i9,  orow + 18);
        unpack_lerp_store(v10, pos10 - (float)i10, orow + 20);
        unpack_lerp_store(v11, pos11 - (float)i11, orow + 22);
    }
}

extern "C" void kernel_launch(void* const* d_in, const int* in_sizes, int n_in,
                              void* d_out, int out_size)
{
    const float* x     = (const float*)d_in[0];
    const float* table = (const float*)d_in[1];
    float*       out   = (float*)d_out;
    int n = in_sizes[0];

    const int smem_bytes = SMEM_PAIRS * (int)sizeof(uint2);  // 65480
    cudaFuncSetAttribute(hashgrid1d_kernel,
                         cudaFuncAttributeMaxDynamicSharedMemorySize, smem_bytes);

    int sm_count = 148;
    cudaDeviceGetAttribute(&sm_count, cudaDevAttrMultiProcessorCount, 0);

    build_pairs_kernel<<<(HASH_N + 255) / 256, 256>>>(table);
    hashgrid1d_kernel<<<sm_count * 3, 512, smem_bytes>>>(x, table, out, n);
}

// round 6
// speedup vs baseline: 2.6132x; 2.6132x over previous
#include <cuda_runtime.h>
#include <cuda_fp16.h>

// HashGrid1D on GB300 — R6.
// Key fix: output stores were ~75% of L1tex work (96B/thread row stride ->
// ~24 wavefronts per STG). Transpose through warp-private smem staging so
// each warp emits its 32 points' 3KB fully coalesced (6x STG.128 rounds).
// Tables: levels 0..8 pair-packed half4 in smem; levels 9..11 pair-packed
// half4 in global (L2-resident), prefetched at iteration start.

#define HASH_N    16384
#define HASH_MASK 16383
#define SMEM_PAIRS 8185             // sum_{l=0}^{8} ((16<<l)+1)
#define TBL_SCALE     16384.0f      // 2^14
#define TBL_INV_SCALE 6.103515625e-05f  // exact 2^-14
#define TBL_BYTES  65488            // 8185*8 padded to 16B
#define STAGE_F4_PER_WARP 224       // 32 threads * 7 float4 (6 data + 1 pad)
#define SMEM_TOTAL (TBL_BYTES + 1024 * 7 * 16)   // 65488 + 114688 = 180176

__device__ uint2 g_pair[3][HASH_N];   // levels 9,10,11: half4 {e0.x,e0.y,e1.x,e1.y}

__device__ __forceinline__ uint2 pack_pair(float2 a, float2 b)
{
    uint2 v;
    __half2 ha = __floats2half2_rn(a.x * TBL_SCALE, a.y * TBL_SCALE);
    __half2 hb = __floats2half2_rn(b.x * TBL_SCALE, b.y * TBL_SCALE);
    v.x = *reinterpret_cast<unsigned*>(&ha);
    v.y = *reinterpret_cast<unsigned*>(&hb);
    return v;
}

__device__ __forceinline__ float2 lerp_pair(uint2 v, float w)
{
    __half2 h0 = *reinterpret_cast<__half2*>(&v.x);
    __half2 h1 = *reinterpret_cast<__half2*>(&v.y);
    float2 e0 = __half22float2(h0);
    float2 e1 = __half22float2(h1);
    float2 r;
    r.x = fmaf(w, e1.x - e0.x, e0.x) * TBL_INV_SCALE;
    r.y = fmaf(w, e1.y - e0.y, e0.y) * TBL_INV_SCALE;
    return r;
}

__global__ void build_pairs_kernel(const float* __restrict__ table)
{
    int i = blockIdx.x * blockDim.x + threadIdx.x;
    if (i >= HASH_N) return;
    int inext = (i + 1) & HASH_MASK;
    #pragma unroll
    for (int k = 0; k < 3; ++k) {
        int l = 9 + k;
        float2 a = *reinterpret_cast<const float2*>(table + i     * 24 + 2 * l);
        float2 b = *reinterpret_cast<const float2*>(table + inext * 24 + 2 * l);
        g_pair[k][i] = pack_pair(a, b);
    }
}

__global__ void __launch_bounds__(1024, 1)
hashgrid1d_kernel(const float* __restrict__ x,
                  const float* __restrict__ table,
                  float* __restrict__ out,
                  int n)
{
    extern __shared__ unsigned char smem_raw[];
    uint2*  spair = reinterpret_cast<uint2*>(smem_raw);              // 8185 pairs
    float4* stage = reinterpret_cast<float4*>(smem_raw + TBL_BYTES); // 1024*7 f4

    const int off[10] = {0, 17, 50, 115, 244, 501, 1014, 2039, 4088, 8185};

    // ---- one-time fill: fp32 table -> scaled half4 pairs (levels 0..8) ----
    for (int e = threadIdx.x; e < SMEM_PAIRS; e += blockDim.x) {
        int l = 0;
        #pragma unroll
        for (int k = 1; k < 9; ++k) l += (e >= off[k]);
        int i = e - off[l];                 // i in [0, 16<<l]; no wrap
        float2 a = *reinterpret_cast<const float2*>(table + i       * 24 + 2 * l);
        float2 b = *reinterpret_cast<const float2*>(table + (i + 1) * 24 + 2 * l);
        spair[e] = pack_pair(a, b);
    }
    __syncthreads();

    const int lane = threadIdx.x & 31;
    float4* my_stage = stage + (threadIdx.x >> 5) * STAGE_F4_PER_WARP;

    int stride = gridDim.x * blockDim.x;
    for (int b = blockIdx.x * blockDim.x + threadIdx.x; b < n; b += stride) {
        float xv = __ldg(x + b);
        float xc = fminf(fmaxf(xv, 0.0f), 1.0f);

        // ---- prefetch divergent global gathers (levels 9..11) ----
        float pos9  = xc * 8192.0f;
        float pos10 = xc * 16384.0f;
        float pos11 = xc * 32768.0f;
        int   i9  = __float2int_rd(pos9);
        int   i10 = __float2int_rd(pos10);
        int   i11 = __float2int_rd(pos11);
        uint2 v9  = __ldg(&g_pair[0][i9  & HASH_MASK]);
        uint2 v10 = __ldg(&g_pair[1][i10 & HASH_MASK]);
        uint2 v11 = __ldg(&g_pair[2][i11 & HASH_MASK]);

        float4 o[6];
        float* of = reinterpret_cast<float*>(o);

        // ---- smem levels 0..8 while gathers are in flight ----
        float res = 16.0f;
        #pragma unroll
        for (int l = 0; l < 9; ++l) {
            float pos = xc * res;
            int   i0  = __float2int_rd(pos);
            float w   = pos - (float)i0;
            float2 r  = lerp_pair(spair[off[l] + i0], w);
            of[2 * l]     = r.x;
            of[2 * l + 1] = r.y;
            res *= 2.0f;
        }
        {
            float2 r = lerp_pair(v9,  pos9  - (float)i9);
            of[18] = r.x; of[19] = r.y;
            r = lerp_pair(v10, pos10 - (float)i10);
            of[20] = r.x; of[21] = r.y;
            r = lerp_pair(v11, pos11 - (float)i11);
            of[22] = r.x; of[23] = r.y;
        }

        // ---- stage row (stride 7 f4: conflict-free, 7 coprime 8) ----
        #pragma unroll
        for (int j = 0; j < 6; ++j) my_stage[lane * 7 + j] = o[j];
        __syncwarp();

        // ---- coalesced emit: warp's 32 points = 3KB contiguous ----
        float4* ob = reinterpret_cast<float4*>(out + (size_t)(b - lane) * 24);
        #pragma unroll
        for (int k = 0; k < 6; ++k) {
            int w4 = lane + 32 * k;               // 0..191
            int p  = (w4 * 2731) >> 14;           // w4 / 6
            int c  = w4 - p * 6;
            ob[w4] = my_stage[p * 7 + c];
        }
        __syncwarp();
    }
}

extern "C" void kernel_launch(void* const* d_in, const int* in_sizes, int n_in,
                              void* d_out, int out_size)
{
    const float* x     = (const float*)d_in[0];
    const float* table = (const float*)d_in[1];
    float*       out   = (float*)d_out;
    int n = in_sizes[0];

    cudaFuncSetAttribute(hashgrid1d_kernel,
                         cudaFuncAttributeMaxDynamicSharedMemorySize, SMEM_TOTAL);

    int sm_count = 148;
    cudaDeviceGetAttribute(&sm_count, cudaDevAttrMultiProcessorCount, 0);

    build_pairs_kernel<<<(HASH_N + 255) / 256, 256>>>(table);
    hashgrid1d_kernel<<<sm_count, 1024, SMEM_TOTAL>>>(x, table, out, n);
}

// round 7
// speedup vs baseline: 2.8617x; 1.0951x over previous
#include <cuda_runtime.h>
#include <cuda_fp16.h>

// HashGrid1D on GB300 — R7.
// L1tex-bound; biggest item was 3 divergent gathers (levels 9..11).
//  - Levels 10+11 fused into ONE gather: combined table indexed by UNHASHED
//    i11 (i10 = i11>>1 exactly). 32769 x 16B = 524KB, L2-resident.
//  - Level 9 moved to smem (unpaired half2, 32.8KB).
//  - Levels 0..8 pair-packed half4 in smem (65.5KB).
//  - Warp-private smem staging transpose for fully coalesced 3KB/warp stores.

#define HASH_MASK 16383
#define COMB_N    32769             // unhashed i11 range 0..32768
#define SMEM_PAIRS 8185             // sum_{l=0}^{8} ((16<<l)+1)
#define L9_ENTRIES 8194             // level 9: indices 0..8193
#define TBL_SCALE     16384.0f      // 2^14
#define TBL_INV_SCALE 6.103515625e-05f  // exact 2^-14

#define PAIR_BYTES  65488           // 8185*8 padded to 16
#define L9_BYTES    32784           // 8194*4 padded to 16
#define STAGE_OFF   (PAIR_BYTES + L9_BYTES)          // 98272, 16B aligned
#define SMEM_TOTAL  (STAGE_OFF + 1024 * 7 * 16)      // 212960

// combined entry: {h2(e10[i10h]), h2(e10[i10h+1]), h2(e11[i11h]), h2(e11[i11h+1])}
__device__ uint4 g_comb[COMB_N];

__device__ __forceinline__ unsigned pack_h2(float2 a)
{
    __half2 h = __floats2half2_rn(a.x * TBL_SCALE, a.y * TBL_SCALE);
    return *reinterpret_cast<unsigned*>(&h);
}

__device__ __forceinline__ float2 lerp_h2pair(unsigned u0, unsigned u1, float w)
{
    float2 e0 = __half22float2(*reinterpret_cast<__half2*>(&u0));
    float2 e1 = __half22float2(*reinterpret_cast<__half2*>(&u1));
    float2 r;
    r.x = fmaf(w, e1.x - e0.x, e0.x) * TBL_INV_SCALE;
    r.y = fmaf(w, e1.y - e0.y, e0.y) * TBL_INV_SCALE;
    return r;
}

__global__ void build_comb_kernel(const float* __restrict__ table)
{
    int j = blockIdx.x * blockDim.x + threadIdx.x;
    if (j >= COMB_N) return;
    int i10 = j >> 1;
    uint4 v;
    v.x = pack_h2(*reinterpret_cast<const float2*>(table + (i10 & HASH_MASK)       * 24 + 20));
    v.y = pack_h2(*reinterpret_cast<const float2*>(table + ((i10 + 1) & HASH_MASK) * 24 + 20));
    v.z = pack_h2(*reinterpret_cast<const float2*>(table + (j & HASH_MASK)         * 24 + 22));
    v.w = pack_h2(*reinterpret_cast<const float2*>(table + ((j + 1) & HASH_MASK)   * 24 + 22));
    g_comb[j] = v;
}

__global__ void __launch_bounds__(1024, 1)
hashgrid1d_kernel(const float* __restrict__ x,
                  const float* __restrict__ table,
                  float* __restrict__ out,
                  int n)
{
    extern __shared__ unsigned char smem_raw[];
    uint2*    spair = reinterpret_cast<uint2*>(smem_raw);                 // lvl 0..8 pairs
    unsigned* s9    = reinterpret_cast<unsigned*>(smem_raw + PAIR_BYTES); // lvl 9 half2
    float4*   stage = reinterpret_cast<float4*>(smem_raw + STAGE_OFF);

    const int off[10] = {0, 17, 50, 115, 244, 501, 1014, 2039, 4088, 8185};

    // ---- fill level 0..8 pair tables ----
    for (int e = threadIdx.x; e < SMEM_PAIRS; e += blockDim.x) {
        int l = 0;
        #pragma unroll
        for (int k = 1; k < 9; ++k) l += (e >= off[k]);
        int i = e - off[l];
        uint2 v;
        v.x = pack_h2(*reinterpret_cast<const float2*>(table + i       * 24 + 2 * l));
        v.y = pack_h2(*reinterpret_cast<const float2*>(table + (i + 1) * 24 + 2 * l));
        spair[e] = v;
    }
    // ---- fill level 9 table (unpaired) ----
    for (int i = threadIdx.x; i < L9_ENTRIES; i += blockDim.x)
        s9[i] = pack_h2(*reinterpret_cast<const float2*>(table + i * 24 + 18));
    __syncthreads();

    const int lane = threadIdx.x & 31;
    float4* my_stage = stage + (threadIdx.x >> 5) * 224;   // 7 f4/thread

    int stride = gridDim.x * blockDim.x;
    for (int b = blockIdx.x * blockDim.x + threadIdx.x; b < n; b += stride) {
        float xv = __ldg(x + b);
        float xc = fminf(fmaxf(xv, 0.0f), 1.0f);

        // ---- single combined gather for levels 10+11 (issue first) ----
        float pos11 = xc * 32768.0f;
        int   i11   = __float2int_rd(pos11);        // 0..32768
        uint4 g     = __ldg(&g_comb[i11]);

        float4 o[6];
        float* of = reinterpret_cast<float*>(o);

        // ---- smem levels 0..8 (pairs) ----
        float res = 16.0f;
        #pragma unroll
        for (int l = 0; l < 9; ++l) {
            float pos = xc * res;
            int   i0  = __float2int_rd(pos);
            float w   = pos - (float)i0;
            uint2 v   = spair[off[l] + i0];
            float2 r  = lerp_h2pair(v.x, v.y, w);
            of[2 * l]     = r.x;
            of[2 * l + 1] = r.y;
            res *= 2.0f;
        }

        // ---- level 9 from smem (unpaired) ----
        {
            float pos = xc * 8192.0f;
            int   i0  = __float2int_rd(pos);
            float w   = pos - (float)i0;
            float2 r  = lerp_h2pair(s9[i0], s9[i0 + 1], w);
            of[18] = r.x; of[19] = r.y;
        }

        // ---- levels 10, 11 from the combined gather ----
        {
            float pos10 = pos11 * 0.5f;
            int   i10   = i11 >> 1;
            float w10   = pos10 - (float)i10;
            float w11   = pos11 - (float)i11;
            float2 r  = lerp_h2pair(g.x, g.y, w10);
            of[20] = r.x; of[21] = r.y;
            r = lerp_h2pair(g.z, g.w, w11);
            of[22] = r.x; of[23] = r.y;
        }

        // ---- stage (stride 7 f4: conflict-free) ----
        #pragma unroll
        for (int j = 0; j < 6; ++j) my_stage[lane * 7 + j] = o[j];
        __syncwarp();

        // ---- coalesced emit: warp's 32 points = 3KB contiguous ----
        float4* ob = reinterpret_cast<float4*>(out + (size_t)(b - lane) * 24);
        #pragma unroll
        for (int k = 0; k < 6; ++k) {
            int w4 = lane + 32 * k;               // 0..191
            int p  = (w4 * 2731) >> 14;           // w4 / 6
            int c  = w4 - p * 6;
            ob[w4] = my_stage[p * 7 + c];
        }
        __syncwarp();
    }
}

extern "C" void kernel_launch(void* const* d_in, const int* in_sizes, int n_in,
                              void* d_out, int out_size)
{
    const float* x     = (const float*)d_in[0];
    const float* table = (const float*)d_in[1];
    float*       out   = (float*)d_out;
    int n = in_sizes[0];

    cudaFuncSetAttribute(hashgrid1d_kernel,
                         cudaFuncAttributeMaxDynamicSharedMemorySize, SMEM_TOTAL);

    int sm_count = 148;
    cudaDeviceGetAttribute(&sm_count, cudaDevAttrMultiProcessorCount, 0);

    build_comb_kernel<<<(COMB_N + 255) / 256, 256>>>(table);
    hashgrid1d_kernel<<<sm_count, 1024, SMEM_TOTAL>>>(x, table, out, n);
}